// round 4
// baseline (speedup 1.0000x reference)
#include <cuda_runtime.h>
#include <cstdint>

#define N_NODES 50000
#define N_EDGES 800000
#define CDIM 128
#define NC (N_NODES * CDIM)
#define E_CAP (N_EDGES + 4 * N_NODES)   // padded edge capacity

typedef unsigned long long u64;

// ---------------- scratch (static device globals; no allocation) ----------------
__device__ int    g_cnt[N_NODES];
__device__ int    g_off[N_NODES + 1];
__device__ int    g_cur[N_NODES];
__device__ int    g_colx[E_CAP];
__device__ float2 g_valx[E_CAP];
__device__ u64    g_agg[N_NODES * CDIM];   // interleaved (ar, ai) pairs

// ---------------- packed f32x2 helpers ----------------
__device__ __forceinline__ u64 pk(float lo, float hi) {
    u64 r; asm("mov.b64 %0, {%1,%2};" : "=l"(r) : "f"(lo), "f"(hi)); return r;
}
__device__ __forceinline__ void upk(u64 v, float& lo, float& hi) {
    asm("mov.b64 {%0,%1}, %2;" : "=f"(lo), "=f"(hi) : "l"(v));
}
__device__ __forceinline__ u64 ffma2(u64 a, u64 b, u64 c) {
    u64 d; asm("fma.rn.f32x2 %0, %1, %2, %3;" : "=l"(d) : "l"(a), "l"(b), "l"(c)); return d;
}

// ---------------- counting sort pipeline (with pad-to-4 offsets) ----------------
__global__ void zero_cnt_kernel() {
    int i = blockIdx.x * blockDim.x + threadIdx.x;
    if (i < N_NODES) g_cnt[i] = 0;
}

__global__ void hist_kernel(const int* __restrict__ row) {
    int e = blockIdx.x * blockDim.x + threadIdx.x;
    if (e < N_EDGES) atomicAdd(&g_cnt[row[e]], 1);
}

// single-block exclusive scan of padded counts
__global__ void scan_kernel() {
    __shared__ int sm[1024];
    const int CH = (N_NODES + 1023) / 1024;  // 49
    int t = threadIdx.x;
    int base = t * CH;
    int s = 0;
    for (int i = 0; i < CH; i++) {
        int idx = base + i;
        if (idx < N_NODES) s += (g_cnt[idx] + 3) & ~3;
    }
    sm[t] = s;
    __syncthreads();
    for (int off = 1; off < 1024; off <<= 1) {
        int v = (t >= off) ? sm[t - off] : 0;
        __syncthreads();
        sm[t] += v;
        __syncthreads();
    }
    int run = sm[t] - s;  // exclusive prefix of padded counts
    for (int i = 0; i < CH; i++) {
        int idx = base + i;
        if (idx < N_NODES) {
            int vp = (g_cnt[idx] + 3) & ~3;
            g_off[idx] = run;
            g_cur[idx] = run;
            run += vp;
        }
    }
    if (t == 1023) g_off[N_NODES] = run;
}

__global__ void scatter_kernel(const int* __restrict__ row, const int* __restrict__ col,
                               const float* __restrict__ lr, const float* __restrict__ li) {
    int e = blockIdx.x * blockDim.x + threadIdx.x;
    if (e < N_EDGES) {
        int r = row[e];
        int p = atomicAdd(&g_cur[r], 1);
        g_colx[p] = col[e];
        g_valx[p] = make_float2(lr[e], li[e]);
    }
}

// fill pad slots (between true end and padded end) with zero-valued edges
__global__ void padfill_kernel() {
    int r = blockIdx.x * blockDim.x + threadIdx.x;
    if (r < N_NODES) {
        int p = g_cur[r];          // true end after scatter
        int e = g_off[r + 1];      // padded end
        for (; p < e; p++) {
            g_colx[p] = 0;
            g_valx[p] = make_float2(0.f, 0.f);
        }
    }
}

// ---------------- SpMM kernel: gather + complex accumulate -> g_agg ----------------
#define S_TPB 256
#define S_WPB 8
#define S_BLOCKS 1563

// slot body: complex FMA on current slot, then pipeline-reload slot metadata + X
#define SB(MD, XR, XI, J) do {                                                 \
    u64 vr2 = pk(MD.y, MD.y), vi2 = pk(MD.z, MD.z), nvi2 = pk(-MD.z, -MD.z);   \
    ar01 = ffma2(vr2,  XR.x, ar01); ar23 = ffma2(vr2,  XR.y, ar23);            \
    ai01 = ffma2(vi2,  XR.x, ai01); ai23 = ffma2(vi2,  XR.y, ai23);            \
    ar01 = ffma2(nvi2, XI.x, ar01); ar23 = ffma2(nvi2, XI.y, ar23);            \
    ai01 = ffma2(vr2,  XI.x, ai01); ai23 = ffma2(vr2,  XI.y, ai23);            \
    int jn = (J) + 4;                                                          \
    if (jn < cnt) {                                                            \
        MD = mrow[jn];                                                         \
        int c = __float_as_int(MD.x);                                          \
        XR = *(const ulonglong2*)(XrL + (c << 7));                             \
        XI = *(const ulonglong2*)(XiL + (c << 7));                             \
    }                                                                          \
} while (0)

__global__ __launch_bounds__(S_TPB)
void spmm_kernel(const float* __restrict__ Xr, const float* __restrict__ Xi) {
    __shared__ float4 meta[S_WPB][32];

    int warp = threadIdx.x >> 5;
    int lane = threadIdx.x & 31;
    float4* mrow = meta[warp];
    const float* XrL = Xr + 4 * lane;
    const float* XiL = Xi + 4 * lane;

    int gw = blockIdx.x * S_WPB + warp;
    int nw = gridDim.x * S_WPB;

    for (int row = gw; row < N_NODES; row += nw) {
        int e0  = g_off[row];
        int deg = g_off[row + 1] - e0;   // multiple of 4
        u64 ar01 = 0, ar23 = 0, ai01 = 0, ai23 = 0;

        for (int base = 0; base < deg; base += 32) {
            int cnt = min(32, deg - base);   // multiple of 4, >= 4
            if (lane < cnt) {
                int    c = g_colx[e0 + base + lane];
                float2 v = g_valx[e0 + base + lane];
                mrow[lane] = make_float4(__int_as_float(c), v.x, v.y, 0.f);
            }
            __syncwarp();

            float4 md0 = mrow[0], md1 = mrow[1], md2 = mrow[2], md3 = mrow[3];
            ulonglong2 xr0, xi0, xr1, xi1, xr2, xi2, xr3, xi3;
            {
                int c0 = __float_as_int(md0.x), c1 = __float_as_int(md1.x);
                int c2 = __float_as_int(md2.x), c3 = __float_as_int(md3.x);
                xr0 = *(const ulonglong2*)(XrL + (c0 << 7));
                xi0 = *(const ulonglong2*)(XiL + (c0 << 7));
                xr1 = *(const ulonglong2*)(XrL + (c1 << 7));
                xi1 = *(const ulonglong2*)(XiL + (c1 << 7));
                xr2 = *(const ulonglong2*)(XrL + (c2 << 7));
                xi2 = *(const ulonglong2*)(XiL + (c2 << 7));
                xr3 = *(const ulonglong2*)(XrL + (c3 << 7));
                xi3 = *(const ulonglong2*)(XiL + (c3 << 7));
            }
            for (int j = 0; j < cnt; j += 4) {
                SB(md0, xr0, xi0, j);
                SB(md1, xr1, xi1, j + 1);
                SB(md2, xr2, xi2, j + 2);
                SB(md3, xr3, xi3, j + 3);
            }
            __syncwarp();   // protect meta before next chunk restages
        }

        // store interleaved (ar, ai) pairs: lane owns channels 4l..4l+3
        float a0, a1, a2, a3, b0, b1, b2, b3;
        upk(ar01, a0, a1); upk(ar23, a2, a3);
        upk(ai01, b0, b1); upk(ai23, b2, b3);
        u64* dst = g_agg + row * CDIM + 4 * lane;
        dst[0] = pk(a0, b0); dst[1] = pk(a1, b1);
        dst[2] = pk(a2, b2); dst[3] = pk(a3, b3);
    }
}

// ---------------- GEMV kernel: out = agg @ W + X (complex pairs) ----------------
#define G_TPB 256
#define G_WPB 8
#define G_RPP 4
#define G_BLOCKS 444   // persistent-ish: ~3 blocks/SM (64KB smem each)

__global__ __launch_bounds__(G_TPB)
void gemv_kernel(const float* __restrict__ Xr, const float* __restrict__ Xi,
                 const float* __restrict__ W, float* __restrict__ out) {
    extern __shared__ float Wsm[];   // [128][128] row-major, 64KB

    int tid = threadIdx.x;
    {
        const float4* src = (const float4*)W;
        float4* dst = (float4*)Wsm;
        for (int i = tid; i < CDIM * CDIM / 4; i += G_TPB) dst[i] = src[i];
    }
    __syncthreads();

    int warp = tid >> 5;
    int lane = tid & 31;
    int gw = blockIdx.x * G_WPB + warp;
    int nw = gridDim.x * G_WPB;
    float* outR = out;
    float* outI = out + NC;

    // 50000 % 4 == 0, so every 4-row group is full
    for (int rb = gw * G_RPP; rb < N_NODES; rb += nw * G_RPP) {
        u64 acc[G_RPP][4];
        const u64* aggRow[G_RPP];
        #pragma unroll
        for (int rr = 0; rr < G_RPP; rr++) {
            int row = rb + rr;
            aggRow[rr] = g_agg + row * CDIM;
            float4 xr4 = *(const float4*)(Xr + row * CDIM + 4 * lane);
            float4 xi4 = *(const float4*)(Xi + row * CDIM + 4 * lane);
            // acc[jl] = (out_real[j], out_imag[j]) pair, residual-initialized
            acc[rr][0] = pk(xr4.x, xi4.x);
            acc[rr][1] = pk(xr4.y, xi4.y);
            acc[rr][2] = pk(xr4.z, xi4.z);
            acc[rr][3] = pk(xr4.w, xi4.w);
        }

        #pragma unroll 4
        for (int k = 0; k < CDIM; k++) {
            float4 w4 = *(const float4*)&Wsm[k * CDIM + 4 * lane];
            u64 wd0 = pk(w4.x, w4.x), wd1 = pk(w4.y, w4.y);
            u64 wd2 = pk(w4.z, w4.z), wd3 = pk(w4.w, w4.w);
            #pragma unroll
            for (int rr = 0; rr < G_RPP; rr++) {
                u64 a = __ldg(aggRow[rr] + k);   // uniform load: (agg_r, agg_i) pair
                acc[rr][0] = ffma2(wd0, a, acc[rr][0]);
                acc[rr][1] = ffma2(wd1, a, acc[rr][1]);
                acc[rr][2] = ffma2(wd2, a, acc[rr][2]);
                acc[rr][3] = ffma2(wd3, a, acc[rr][3]);
            }
        }

        #pragma unroll
        for (int rr = 0; rr < G_RPP; rr++) {
            int row = rb + rr;
            float4 r4, i4;
            upk(acc[rr][0], r4.x, i4.x);
            upk(acc[rr][1], r4.y, i4.y);
            upk(acc[rr][2], r4.z, i4.z);
            upk(acc[rr][3], r4.w, i4.w);
            *(float4*)(outR + row * CDIM + 4 * lane) = r4;
            *(float4*)(outI + row * CDIM + 4 * lane) = i4;
        }
    }
}

// ---------------- launch (7 launches; ncu -s 5 lands on spmm_kernel) ----------------
extern "C" void kernel_launch(void* const* d_in, const int* in_sizes, int n_in,
                              void* d_out, int out_size) {
    const float* Xr = (const float*)d_in[0];
    const float* Xi = (const float*)d_in[1];
    const float* Lr = (const float*)d_in[2];
    const float* Li = (const float*)d_in[3];
    const float* W  = (const float*)d_in[4];
    const int*   row = (const int*)d_in[5];
    const int*   col = (const int*)d_in[6];
    float* out = (float*)d_out;

    zero_cnt_kernel<<<(N_NODES + 255) / 256, 256>>>();                  // 1
    hist_kernel<<<(N_EDGES + 255) / 256, 256>>>(row);                   // 2
    scan_kernel<<<1, 1024>>>();                                         // 3
    scatter_kernel<<<(N_EDGES + 255) / 256, 256>>>(row, col, Lr, Li);   // 4
    padfill_kernel<<<(N_NODES + 255) / 256, 256>>>();                   // 5
    spmm_kernel<<<S_BLOCKS, S_TPB>>>(Xr, Xi);                           // 6 <- profiled
    cudaFuncSetAttribute(gemv_kernel, cudaFuncAttributeMaxDynamicSharedMemorySize,
                         CDIM * CDIM * 4);
    gemv_kernel<<<G_BLOCKS, G_TPB, CDIM * CDIM * 4>>>(Xr, Xi, W, out);  // 7
}